// round 4
// baseline (speedup 1.0000x reference)
#include <cuda_runtime.h>
#include <cstdint>

// Problem constants (fixed shapes)
#define B_    240
#define S_    64
#define H_    768
#define NH_   12
#define HD_   64
#define L0_   384
#define L1_   128
#define LT_   576          // L0+L1+S
#define BS_   8            // cache0 batch = 240/30
#define OUTSZ (B_*S_*H_)   // 11796480

// scratch for q in [B, nh, S, hd] layout (fp32)
__device__ float g_q[B_ * NH_ * S_ * HD_];

// ---------------------------------------------------------------------------
// helpers
// ---------------------------------------------------------------------------
__device__ __forceinline__ uint32_t f2tf(float f) {
    uint32_t r;
    asm("cvt.rna.tf32.f32 %0, %1;" : "=r"(r) : "f"(f));
    return r;
}
__device__ __forceinline__ uint32_t smem_u32(const void* p) {
    uint32_t a;
    asm("{ .reg .u64 t; cvta.to.shared.u64 t, %1; cvt.u32.u64 %0, t; }"
        : "=r"(a) : "l"(p));
    return a;
}
#define CP_ASYNC16(saddr, gaddr) \
    asm volatile("cp.async.cg.shared.global [%0], [%1], 16;" \
                 :: "r"(saddr), "l"(gaddr))
#define CP_COMMIT()  asm volatile("cp.async.commit_group;")
#define CP_WAIT2()   asm volatile("cp.async.wait_group 2;")

// D(16x8,f32) += A(16x8,tf32) * B(8x8,tf32)
__device__ __forceinline__ void mma8(float* d, const uint32_t* a, const uint32_t* b) {
    asm volatile(
        "mma.sync.aligned.m16n8k8.row.col.f32.tf32.tf32.f32 "
        "{%0,%1,%2,%3}, {%4,%5,%6,%7}, {%8,%9}, {%0,%1,%2,%3};"
        : "+f"(d[0]), "+f"(d[1]), "+f"(d[2]), "+f"(d[3])
        : "r"(a[0]), "r"(a[1]), "r"(a[2]), "r"(a[3]), "r"(b[0]), "r"(b[1]));
}

// ===========================================================================
// Kernel 1: QKV projection.  C[15360,768] = hidden @ W^T + bias,
// written in [B, nh, S, hd] layout.  tf32 mma.sync, 128x128 CTA tile, BK=32,
// 3-stage cp.async pipeline (fp32 in smem, cvt at fragment load).
// grid = (6 n-tiles, 120 m-tiles, 3 matrices), 256 threads (8 warps, 64x32).
// ===========================================================================
#define QPAD 36                 // 32 + 4: pad ≡ 4 mod 32, frag loads conflict-free
#define QSTG (128 * QPAD)       // words per tile per stage
#define QKV_SMEM (6 * QSTG * 4) // 3 stages x (A + B) = 110592 bytes

__global__ __launch_bounds__(256, 2) void qkv_mma_kernel(
    const float* __restrict__ hidden,
    const float* __restrict__ Wq, const float* __restrict__ bq,
    const float* __restrict__ Wk, const float* __restrict__ bk,
    const float* __restrict__ Wv, const float* __restrict__ bv,
    float* __restrict__ kout, float* __restrict__ vout)
{
    extern __shared__ char smem[];
    float* As = (float*)smem;          // 3 stages x QSTG
    float* Bs = As + 3 * QSTG;

    const int tid = threadIdx.x, lane = tid & 31, warp = tid >> 5;
    const int gid = lane >> 2, tig = lane & 3;
    const int nt = blockIdx.x, mt = blockIdx.y, sel = blockIdx.z;

    const float* W    = (sel == 0) ? Wq : (sel == 1) ? Wk : Wv;
    const float* bias = (sel == 0) ? bq : (sel == 1) ? bk : bv;
    float* dst        = (sel == 0) ? g_q : (sel == 1) ? kout : vout;

    const int m0 = mt * 128, n0 = nt * 128;
    const int wm = (warp >> 2) * 64, wn = (warp & 3) * 32;

    // per-thread copy coordinates: 4 x 16B pieces per matrix per chunk
    const int cr = tid >> 1;            // 0..127 row (2 threads per row)
    const int cc = (tid & 1) * 16;      // col offset (floats): 0 or 16
    const uint32_t sA0 = smem_u32(&As[cr * QPAD + cc]);
    const uint32_t sB0 = smem_u32(&Bs[cr * QPAD + cc]);
    const float* gA0 = hidden + (size_t)(m0 + cr) * H_ + cc;
    const float* gB0 = W      + (size_t)(n0 + cr) * H_ + cc;

    float acc[4][4][4];
#pragma unroll
    for (int mi = 0; mi < 4; mi++)
#pragma unroll
        for (int ni = 0; ni < 4; ni++)
#pragma unroll
            for (int j = 0; j < 4; j++) acc[mi][ni][j] = 0.f;

    // prologue: issue 3 stages
#pragma unroll
    for (int s = 0; s < 3; s++) {
        const int k0 = s * 32;
        const uint32_t stoff = (uint32_t)(s * QSTG * 4);
#pragma unroll
        for (int p = 0; p < 4; p++) {   // 4 x 16B = 2 col-groups x ... (cc covers 16 floats)
            CP_ASYNC16(sA0 + stoff + p * 16, gA0 + k0 + p * 4);
            CP_ASYNC16(sB0 + stoff + p * 16, gB0 + k0 + p * 4);
        }
        CP_COMMIT();
    }

    for (int i = 0; i < 24; i++) {
        CP_WAIT2();
        __syncthreads();
        const int st = i % 3;
        const float* AsS = As + st * QSTG;
        const float* BsS = Bs + st * QSTG;
#pragma unroll
        for (int kk = 0; kk < 4; kk++) {
            const int c = kk * 8 + tig;
            uint32_t a[4][4], bf[4][2];
#pragma unroll
            for (int mi = 0; mi < 4; mi++) {
                int r = wm + mi * 16 + gid;
                a[mi][0] = f2tf(AsS[r * QPAD + c]);
                a[mi][1] = f2tf(AsS[(r + 8) * QPAD + c]);
                a[mi][2] = f2tf(AsS[r * QPAD + c + 4]);
                a[mi][3] = f2tf(AsS[(r + 8) * QPAD + c + 4]);
            }
#pragma unroll
            for (int ni = 0; ni < 4; ni++) {
                int rn = wn + ni * 8 + gid;
                bf[ni][0] = f2tf(BsS[rn * QPAD + c]);
                bf[ni][1] = f2tf(BsS[rn * QPAD + c + 4]);
            }
#pragma unroll
            for (int mi = 0; mi < 4; mi++)
#pragma unroll
                for (int ni = 0; ni < 4; ni++)
                    mma8(acc[mi][ni], a[mi], bf[ni]);
        }
        __syncthreads();
        if (i + 3 < 24) {
            const int k0 = (i + 3) * 32;
            const uint32_t stoff = (uint32_t)(st * QSTG * 4);
#pragma unroll
            for (int p = 0; p < 4; p++) {
                CP_ASYNC16(sA0 + stoff + p * 16, gA0 + k0 + p * 4);
                CP_ASYNC16(sB0 + stoff + p * 16, gB0 + k0 + p * 4);
            }
        }
        CP_COMMIT();
    }

    // epilogue: bias + store into [B, nh, S, hd]
#pragma unroll
    for (int ni = 0; ni < 4; ni++) {
        int gn = n0 + wn + ni * 8 + 2 * tig;
        float b0 = __ldg(bias + gn), b1 = __ldg(bias + gn + 1);
        int hh = gn >> 6, dd = gn & 63;
#pragma unroll
        for (int mi = 0; mi < 4; mi++) {
            int gm = m0 + wm + mi * 16 + gid;
            int bb = gm >> 6, ss = gm & 63;
            float2 v0 = { acc[mi][ni][0] + b0, acc[mi][ni][1] + b1 };
            *(float2*)(dst + (((size_t)bb * NH_ + hh) * S_ + ss) * HD_ + dd) = v0;
            int gm2 = gm + 8;
            bb = gm2 >> 6; ss = gm2 & 63;
            float2 v1 = { acc[mi][ni][2] + b0, acc[mi][ni][3] + b1 };
            *(float2*)(dst + (((size_t)bb * NH_ + hh) * S_ + ss) * HD_ + dd) = v1;
        }
    }
}

// ===========================================================================
// Kernel 2: attention via tf32 mma.sync + online softmax.
// One block per (b,h), 4 warps x 16 q-rows. 64-key tiles in smem.
// Q fragments loaded directly from gmem; P stays in registers (quad shfl).
// ===========================================================================
#define APAD 72                   // 64 + 8: both frag patterns conflict-free
#define ATTN_SMEM ((2 * 64 * APAD + 64) * 4)

__global__ __launch_bounds__(128) void attn_mma_kernel(
    const float* __restrict__ kout, const float* __restrict__ vout,
    const float* __restrict__ c0k,  const float* __restrict__ c0v,
    const float* __restrict__ c1k,  const float* __restrict__ c1v,
    const float* __restrict__ mask, float* __restrict__ out)
{
    extern __shared__ char smem[];
    uint32_t* ks = (uint32_t*)smem;         // 64 x APAD
    uint32_t* vs = ks + 64 * APAD;          // 64 x APAD
    float* msm   = (float*)(vs + 64 * APAD);

    const unsigned FULL = 0xffffffffu;
    const int bh = blockIdx.x, b = bh / NH_, h = bh % NH_;
    const int tid = threadIdx.x, lane = tid & 31, warp = tid >> 5;
    const int gid = lane >> 2, tig = lane & 3;

    // Q fragments direct from gmem (pre-scaled by 1/8)
    uint32_t qf[8][4];
    {
        const float* qp = g_q + (size_t)bh * S_ * HD_;
        const int r = warp * 16 + gid;
#pragma unroll
        for (int kk = 0; kk < 8; kk++) {
            int c = kk * 8 + tig;
            qf[kk][0] = f2tf(qp[r * HD_ + c] * 0.125f);
            qf[kk][1] = f2tf(qp[(r + 8) * HD_ + c] * 0.125f);
            qf[kk][2] = f2tf(qp[r * HD_ + c + 4] * 0.125f);
            qf[kk][3] = f2tf(qp[(r + 8) * HD_ + c + 4] * 0.125f);
        }
    }

    float o[8][4];
#pragma unroll
    for (int nd = 0; nd < 8; nd++)
#pragma unroll
        for (int j = 0; j < 4; j++) o[nd][j] = 0.f;
    float m0 = -1e30f, m1 = -1e30f, l0 = 0.f, l1 = 0.f;

    const float* maskb = mask + (size_t)b * LT_;

    for (int seg = 0; seg < 3; seg++) {
        const float *kb, *vb;
        int len, posbase;
        if (seg == 0) {
            size_t off = ((size_t)(b % BS_) * NH_ + h) * L0_ * HD_;
            kb = c0k + off; vb = c0v + off; len = L0_; posbase = 0;
        } else if (seg == 1) {
            size_t off = ((size_t)b * NH_ + h) * L1_ * HD_;
            kb = c1k + off; vb = c1v + off; len = L1_; posbase = L0_;
        } else {
            size_t off = ((size_t)b * NH_ + h) * S_ * HD_;
            kb = kout + off; vb = vout + off; len = S_; posbase = L0_ + L1_;
        }

        for (int t = 0; t < len; t += 64) {
            __syncthreads();
            // stage 64 keys of K then V: load-all-then-store for MLP
            {
                float4 stash[8];
#pragma unroll
                for (int p = 0; p < 8; p++) {
                    int idx = p * 128 + tid;
                    stash[p] = *(const float4*)(kb + (size_t)(t + (idx >> 4)) * HD_ + (idx & 15) * 4);
                }
#pragma unroll
                for (int p = 0; p < 8; p++) {
                    int idx = p * 128 + tid;
                    uint32_t* pk = &ks[(idx >> 4) * APAD + (idx & 15) * 4];
                    pk[0] = f2tf(stash[p].x); pk[1] = f2tf(stash[p].y);
                    pk[2] = f2tf(stash[p].z); pk[3] = f2tf(stash[p].w);
                }
#pragma unroll
                for (int p = 0; p < 8; p++) {
                    int idx = p * 128 + tid;
                    stash[p] = *(const float4*)(vb + (size_t)(t + (idx >> 4)) * HD_ + (idx & 15) * 4);
                }
#pragma unroll
                for (int p = 0; p < 8; p++) {
                    int idx = p * 128 + tid;
                    uint32_t* pv = &vs[(idx >> 4) * APAD + (idx & 15) * 4];
                    pv[0] = f2tf(stash[p].x); pv[1] = f2tf(stash[p].y);
                    pv[2] = f2tf(stash[p].z); pv[3] = f2tf(stash[p].w);
                }
            }
            if (tid < 64) msm[tid] = maskb[posbase + t + tid];
            __syncthreads();

            // scores: S[16 rows][64 keys] per warp
            float sc[8][4];
#pragma unroll
            for (int nb = 0; nb < 8; nb++) {
                sc[nb][0] = sc[nb][1] = sc[nb][2] = sc[nb][3] = 0.f;
#pragma unroll
                for (int kk = 0; kk < 8; kk++) {
                    uint32_t bf[2];
                    int rn = nb * 8 + gid, c = kk * 8 + tig;
                    bf[0] = ks[rn * APAD + c];
                    bf[1] = ks[rn * APAD + c + 4];
                    mma8(sc[nb], qf[kk], bf);
                }
                float mk0 = msm[nb * 8 + 2 * tig], mk1 = msm[nb * 8 + 2 * tig + 1];
                sc[nb][0] += mk0; sc[nb][1] += mk1;
                sc[nb][2] += mk0; sc[nb][3] += mk1;
            }

            // online softmax (rows r = gid and r+8)
            float tm0 = -1e30f, tm1 = -1e30f;
#pragma unroll
            for (int nb = 0; nb < 8; nb++) {
                tm0 = fmaxf(tm0, fmaxf(sc[nb][0], sc[nb][1]));
                tm1 = fmaxf(tm1, fmaxf(sc[nb][2], sc[nb][3]));
            }
            tm0 = fmaxf(tm0, __shfl_xor_sync(FULL, tm0, 1));
            tm0 = fmaxf(tm0, __shfl_xor_sync(FULL, tm0, 2));
            tm1 = fmaxf(tm1, __shfl_xor_sync(FULL, tm1, 1));
            tm1 = fmaxf(tm1, __shfl_xor_sync(FULL, tm1, 2));
            float nm0 = fmaxf(m0, tm0), nm1 = fmaxf(m1, tm1);
            float cr0 = __expf(m0 - nm0), cr1 = __expf(m1 - nm1);
            m0 = nm0; m1 = nm1;
            l0 *= cr0; l1 *= cr1;

            // exp, accumulate l, convert in place (sc regs hold tf32 bits)
#pragma unroll
            for (int nb = 0; nb < 8; nb++) {
                float p0 = __expf(sc[nb][0] - m0), p1 = __expf(sc[nb][1] - m0);
                float p2 = __expf(sc[nb][2] - m1), p3 = __expf(sc[nb][3] - m1);
                l0 += p0 + p1; l1 += p2 + p3;
                sc[nb][0] = __uint_as_float(f2tf(p0));
                sc[nb][1] = __uint_as_float(f2tf(p1));
                sc[nb][2] = __uint_as_float(f2tf(p2));
                sc[nb][3] = __uint_as_float(f2tf(p3));
            }
#pragma unroll
            for (int nd = 0; nd < 8; nd++) {
                o[nd][0] *= cr0; o[nd][1] *= cr0;
                o[nd][2] *= cr1; o[nd][3] *= cr1;
            }

            // P (C-layout) -> A-fragments via quad shuffles, then P @ V
            const int srcA = (lane & ~3) | (tig >> 1);
            const int srcB = srcA + 2;
            const bool pk = tig & 1;
#pragma unroll
            for (int kc = 0; kc < 8; kc++) {
                uint32_t t0 = __shfl_sync(FULL, __float_as_uint(sc[kc][0]), srcA);
                uint32_t t1 = __shfl_sync(FULL, __float_as_uint(sc[kc][1]), srcA);
                uint32_t t2 = __shfl_sync(FULL, __float_as_uint(sc[kc][2]), srcA);
                uint32_t t3 = __shfl_sync(FULL, __float_as_uint(sc[kc][3]), srcA);
                uint32_t u0 = __shfl_sync(FULL, __float_as_uint(sc[kc][0]), srcB);
                uint32_t u1 = __shfl_sync(FULL, __float_as_uint(sc[kc][1]), srcB);
                uint32_t u2 = __shfl_sync(FULL, __float_as_uint(sc[kc][2]), srcB);
                uint32_t u3 = __shfl_sync(FULL, __float_as_uint(sc[kc][3]), srcB);
                uint32_t pa[4] = { pk ? t1 : t0, pk ? t3 : t2,
                                   pk ? u1 : u0, pk ? u3 : u2 };
#pragma unroll
                for (int nd = 0; nd < 8; nd++) {
                    uint32_t vf[2];
                    int rk = kc * 8 + tig, cn = nd * 8 + gid;
                    vf[0] = vs[rk * APAD + cn];
                    vf[1] = vs[(rk + 4) * APAD + cn];
                    mma8(o[nd], pa, vf);
                }
            }
        }
    }

    l0 += __shfl_xor_sync(FULL, l0, 1);
    l0 += __shfl_xor_sync(FULL, l0, 2);
    l1 += __shfl_xor_sync(FULL, l1, 1);
    l1 += __shfl_xor_sync(FULL, l1, 2);
    float i0 = 1.f / l0, i1 = 1.f / l1;

    const int s = warp * 16 + gid;
    float* ob  = out + ((size_t)b * S_ + s) * H_ + h * HD_;
    float* ob2 = out + ((size_t)b * S_ + s + 8) * H_ + h * HD_;
#pragma unroll
    for (int nd = 0; nd < 8; nd++) {
        int d = nd * 8 + 2 * tig;
        float2 v0 = { o[nd][0] * i0, o[nd][1] * i0 };
        float2 v1 = { o[nd][2] * i1, o[nd][3] * i1 };
        *(float2*)(ob + d)  = v0;
        *(float2*)(ob2 + d) = v1;
    }
}

// ---------------------------------------------------------------------------
extern "C" void kernel_launch(void* const* d_in, const int* in_sizes, int n_in,
                              void* d_out, int out_size)
{
    const float* hidden = (const float*)d_in[0];
    const float* mask   = (const float*)d_in[1];
    const float* Wq     = (const float*)d_in[2];
    const float* bq     = (const float*)d_in[3];
    const float* Wk     = (const float*)d_in[4];
    const float* bk     = (const float*)d_in[5];
    const float* Wv     = (const float*)d_in[6];
    const float* bv     = (const float*)d_in[7];
    const float* c0k    = (const float*)d_in[8];
    const float* c0v    = (const float*)d_in[9];
    const float* c1k    = (const float*)d_in[10];
    const float* c1v    = (const float*)d_in[11];

    float* out  = (float*)d_out;
    float* kout = out + (size_t)OUTSZ;
    float* vout = out + (size_t)2 * OUTSZ;

    static int inited = 0;
    if (!inited) {
        cudaFuncSetAttribute(qkv_mma_kernel,
                             cudaFuncAttributeMaxDynamicSharedMemorySize, QKV_SMEM);
        cudaFuncSetAttribute(attn_mma_kernel,
                             cudaFuncAttributeMaxDynamicSharedMemorySize, ATTN_SMEM);
        inited = 1;
    }

    dim3 g1(6, 120, 3);
    qkv_mma_kernel<<<g1, 256, QKV_SMEM>>>(hidden, Wq, bq, Wk, bk, Wv, bv, kout, vout);

    attn_mma_kernel<<<B_ * NH_, 128, ATTN_SMEM>>>(kout, vout, c0k, c0v, c1k, c1v, mask, out);
}

// round 5
// speedup vs baseline: 1.3865x; 1.3865x over previous
#include <cuda_runtime.h>
#include <cstdint>

// Problem constants (fixed shapes)
#define B_    240
#define S_    64
#define H_    768
#define NH_   12
#define HD_   64
#define L0_   384
#define L1_   128
#define LT_   576          // L0+L1+S
#define BS_   8            // cache0 batch = 240/30
#define OUTSZ (B_*S_*H_)   // 11796480

// scratch for q in [B, nh, S, hd] layout (fp32)
__device__ float g_q[B_ * NH_ * S_ * HD_];

// ---------------------------------------------------------------------------
// helpers
// ---------------------------------------------------------------------------
__device__ __forceinline__ uint32_t f2tf(float f) {
    uint32_t r;
    asm("cvt.rna.tf32.f32 %0, %1;" : "=r"(r) : "f"(f));
    return r;
}
__device__ __forceinline__ uint32_t smem_u32(const void* p) {
    uint32_t a;
    asm("{ .reg .u64 t; cvta.to.shared.u64 t, %1; cvt.u32.u64 %0, t; }"
        : "=r"(a) : "l"(p));
    return a;
}
#define CP_ASYNC16(saddr, gaddr) \
    asm volatile("cp.async.cg.shared.global [%0], [%1], 16;" \
                 :: "r"(saddr), "l"(gaddr))
#define CP_COMMIT()  asm volatile("cp.async.commit_group;")
#define CP_WAIT2()   asm volatile("cp.async.wait_group 2;")

// D(16x8,f32) += A(16x8,tf32) * B(8x8,tf32)
__device__ __forceinline__ void mma8(float* d, const uint32_t* a, const uint32_t* b) {
    asm volatile(
        "mma.sync.aligned.m16n8k8.row.col.f32.tf32.tf32.f32 "
        "{%0,%1,%2,%3}, {%4,%5,%6,%7}, {%8,%9}, {%0,%1,%2,%3};"
        : "+f"(d[0]), "+f"(d[1]), "+f"(d[2]), "+f"(d[3])
        : "r"(a[0]), "r"(a[1]), "r"(a[2]), "r"(a[3]), "r"(b[0]), "r"(b[1]));
}

// ===========================================================================
// Kernel 1: QKV projection.  C[15360,768] = hidden @ W^T + bias,
// written in [B, nh, S, hd] layout.  tf32 mma.sync, 128x128 CTA tile, BK=32.
// 3-stage cp.async pipeline; in-place fp32 -> tf32 convert pass per chunk
// (cvt once per element); compute reads tf32 fragments with no cvt.
// grid = (6 n-tiles, 120 m-tiles, 3 matrices), 256 threads (8 warps, 64x32).
// ===========================================================================
#define QPAD 36                    // 32 + 4: frag LDS conflict-free
#define QWORDS (128 * QPAD)        // words per matrix per stage (4608)
#define QKV_SMEM (6 * QWORDS * 4)  // 3 stages x (A+B) = 110592 bytes

__global__ __launch_bounds__(256, 2) void qkv_mma_kernel(
    const float* __restrict__ hidden,
    const float* __restrict__ Wq, const float* __restrict__ bq,
    const float* __restrict__ Wk, const float* __restrict__ bk,
    const float* __restrict__ Wv, const float* __restrict__ bv,
    float* __restrict__ kout, float* __restrict__ vout)
{
    extern __shared__ char smem[];
    // layout: A stages 0..2 at s*QWORDS, B stages at (3+s)*QWORDS (words)
    uint32_t* smw = (uint32_t*)smem;

    const int tid = threadIdx.x, lane = tid & 31, warp = tid >> 5;
    const int gid = lane >> 2, tig = lane & 3;
    const int nt = blockIdx.x, mt = blockIdx.y, sel = blockIdx.z;

    const float* W    = (sel == 0) ? Wq : (sel == 1) ? Wk : Wv;
    const float* bias = (sel == 0) ? bq : (sel == 1) ? bk : bv;
    float* dst        = (sel == 0) ? g_q : (sel == 1) ? kout : vout;

    const int m0 = mt * 128, n0 = nt * 128;
    const int wm = (warp >> 2) * 64, wn = (warp & 3) * 32;

    // copy coords: 2 threads per row, 16 floats each (4 x cp.async 16B)
    const int cr = tid >> 1;            // 0..127
    const int cc = (tid & 1) * 16;      // 0 or 16
    const uint32_t sbase = smem_u32(smem);
    const uint32_t sAoff = (uint32_t)((cr * QPAD + cc) * 4);
    const float* gA0 = hidden + (size_t)(m0 + cr) * H_ + cc;
    const float* gB0 = W      + (size_t)(n0 + cr) * H_ + cc;

    float acc[4][4][4];
#pragma unroll
    for (int mi = 0; mi < 4; mi++)
#pragma unroll
        for (int ni = 0; ni < 4; ni++)
#pragma unroll
            for (int j = 0; j < 4; j++) acc[mi][ni][j] = 0.f;

    // prologue: issue 3 stages
#pragma unroll
    for (int s = 0; s < 3; s++) {
        const int k0 = s * 32;
        const uint32_t aoff = sbase + (uint32_t)(s * QWORDS * 4) + sAoff;
        const uint32_t boff = sbase + (uint32_t)((3 + s) * QWORDS * 4) + sAoff;
#pragma unroll
        for (int p = 0; p < 4; p++) {
            CP_ASYNC16(aoff + p * 16, gA0 + k0 + p * 4);
            CP_ASYNC16(boff + p * 16, gB0 + k0 + p * 4);
        }
        CP_COMMIT();
    }

    for (int i = 0; i < 24; i++) {
        const int st = i % 3;
        CP_WAIT2();
        __syncthreads();

        // in-place cvt pass: 4096 real words per matrix, 16 per thread
        uint32_t* stA = smw + st * QWORDS;
        uint32_t* stB = smw + (3 + st) * QWORDS;
#pragma unroll
        for (int p = 0; p < 4; p++) {
            int w = p * 1024 + tid * 4;
            int ad = (w >> 5) * QPAD + (w & 31);
            float4 va = *(float4*)&stA[ad];
            uint4 ta = { f2tf(va.x), f2tf(va.y), f2tf(va.z), f2tf(va.w) };
            *(uint4*)&stA[ad] = ta;
            float4 vb = *(float4*)&stB[ad];
            uint4 tb = { f2tf(vb.x), f2tf(vb.y), f2tf(vb.z), f2tf(vb.w) };
            *(uint4*)&stB[ad] = tb;
        }
        __syncthreads();

        // compute from tf32 stage
#pragma unroll
        for (int kk = 0; kk < 4; kk++) {
            const int c = kk * 8 + tig;
            uint32_t a[4][4], bf[4][2];
#pragma unroll
            for (int mi = 0; mi < 4; mi++) {
                int r = wm + mi * 16 + gid;
                a[mi][0] = stA[r * QPAD + c];
                a[mi][1] = stA[(r + 8) * QPAD + c];
                a[mi][2] = stA[r * QPAD + c + 4];
                a[mi][3] = stA[(r + 8) * QPAD + c + 4];
            }
#pragma unroll
            for (int ni = 0; ni < 4; ni++) {
                int rn = wn + ni * 8 + gid;
                bf[ni][0] = stB[rn * QPAD + c];
                bf[ni][1] = stB[rn * QPAD + c + 4];
            }
#pragma unroll
            for (int mi = 0; mi < 4; mi++)
#pragma unroll
                for (int ni = 0; ni < 4; ni++)
                    mma8(acc[mi][ni], a[mi], bf[ni]);
        }
        __syncthreads();

        // refill this stage for chunk i+3 (after all reads done)
        if (i + 3 < 24) {
            const int k0 = (i + 3) * 32;
            const uint32_t aoff = sbase + (uint32_t)(st * QWORDS * 4) + sAoff;
            const uint32_t boff = sbase + (uint32_t)((3 + st) * QWORDS * 4) + sAoff;
#pragma unroll
            for (int p = 0; p < 4; p++) {
                CP_ASYNC16(aoff + p * 16, gA0 + k0 + p * 4);
                CP_ASYNC16(boff + p * 16, gB0 + k0 + p * 4);
            }
        }
        CP_COMMIT();   // empty groups in tail keep wait_group bookkeeping exact
    }

    // epilogue: bias + store into [B, nh, S, hd]
#pragma unroll
    for (int ni = 0; ni < 4; ni++) {
        int gn = n0 + wn + ni * 8 + 2 * tig;
        float b0 = __ldg(bias + gn), b1 = __ldg(bias + gn + 1);
        int hh = gn >> 6, dd = gn & 63;
#pragma unroll
        for (int mi = 0; mi < 4; mi++) {
            int gm = m0 + wm + mi * 16 + gid;
            int bb = gm >> 6, ss = gm & 63;
            float2 v0 = { acc[mi][ni][0] + b0, acc[mi][ni][1] + b1 };
            *(float2*)(dst + (((size_t)bb * NH_ + hh) * S_ + ss) * HD_ + dd) = v0;
            int gm2 = gm + 8;
            bb = gm2 >> 6; ss = gm2 & 63;
            float2 v1 = { acc[mi][ni][2] + b0, acc[mi][ni][3] + b1 };
            *(float2*)(dst + (((size_t)bb * NH_ + hh) * S_ + ss) * HD_ + dd) = v1;
        }
    }
}

// ===========================================================================
// Kernel 2: attention via tf32 mma.sync + online softmax (R3 version).
// One block per (b,h), 4 warps x 16 q-rows. 32-key K/V tiles in smem.
// P stays in registers: C-fragment -> A-fragment via quad shuffles.
// ===========================================================================
#define KPAD 72   // 64 + 8: stride ≡ 8 (mod 32) → conflict-free frag LDS

__global__ __launch_bounds__(128) void attn_mma_kernel(
    const float* __restrict__ kout, const float* __restrict__ vout,
    const float* __restrict__ c0k,  const float* __restrict__ c0v,
    const float* __restrict__ c1k,  const float* __restrict__ c1v,
    const float* __restrict__ mask, float* __restrict__ out)
{
    __shared__ uint32_t qs[64 * KPAD];
    __shared__ uint32_t ks[32 * KPAD];
    __shared__ uint32_t vs[32 * KPAD];
    __shared__ float msm[32];

    const unsigned FULL = 0xffffffffu;
    const int bh = blockIdx.x, b = bh / NH_, h = bh % NH_;
    const int tid = threadIdx.x, lane = tid & 31, warp = tid >> 5;
    const int gid = lane >> 2, tig = lane & 3;

    // stage Q (pre-scaled by 1/sqrt(64)) as tf32
    {
        const float* qp = g_q + (size_t)bh * S_ * HD_;
#pragma unroll
        for (int i = 0; i < 8; i++) {
            int idx = i * 128 + tid;
            int r = idx >> 4, c = (idx & 15) * 4;
            float4 v = *(const float4*)(qp + r * HD_ + c);
            uint32_t* p = &qs[r * KPAD + c];
            p[0] = f2tf(v.x * 0.125f); p[1] = f2tf(v.y * 0.125f);
            p[2] = f2tf(v.z * 0.125f); p[3] = f2tf(v.w * 0.125f);
        }
    }
    __syncthreads();

    uint32_t qf[8][4];
    {
        const int r = warp * 16 + gid;
#pragma unroll
        for (int kk = 0; kk < 8; kk++) {
            int c = kk * 8 + tig;
            qf[kk][0] = qs[r * KPAD + c];
            qf[kk][1] = qs[(r + 8) * KPAD + c];
            qf[kk][2] = qs[r * KPAD + c + 4];
            qf[kk][3] = qs[(r + 8) * KPAD + c + 4];
        }
    }

    float o[8][4];
#pragma unroll
    for (int nd = 0; nd < 8; nd++)
#pragma unroll
        for (int j = 0; j < 4; j++) o[nd][j] = 0.f;
    float m0 = -1e30f, m1 = -1e30f, l0 = 0.f, l1 = 0.f;

    const float* maskb = mask + (size_t)b * LT_;

    for (int seg = 0; seg < 3; seg++) {
        const float *kb, *vb;
        int len, posbase;
        if (seg == 0) {
            size_t off = ((size_t)(b % BS_) * NH_ + h) * L0_ * HD_;
            kb = c0k + off; vb = c0v + off; len = L0_; posbase = 0;
        } else if (seg == 1) {
            size_t off = ((size_t)b * NH_ + h) * L1_ * HD_;
            kb = c1k + off; vb = c1v + off; len = L1_; posbase = L0_;
        } else {
            size_t off = ((size_t)b * NH_ + h) * S_ * HD_;
            kb = kout + off; vb = vout + off; len = S_; posbase = L0_ + L1_;
        }

        for (int t = 0; t < len; t += 32) {
            __syncthreads();
#pragma unroll
            for (int i = 0; i < 4; i++) {
                int idx = i * 128 + tid;
                int r = idx >> 4, c = (idx & 15) * 4;
                float4 kv = *(const float4*)(kb + (size_t)(t + r) * HD_ + c);
                uint32_t* pk = &ks[r * KPAD + c];
                pk[0] = f2tf(kv.x); pk[1] = f2tf(kv.y); pk[2] = f2tf(kv.z); pk[3] = f2tf(kv.w);
                float4 vv = *(const float4*)(vb + (size_t)(t + r) * HD_ + c);
                uint32_t* pv = &vs[r * KPAD + c];
                pv[0] = f2tf(vv.x); pv[1] = f2tf(vv.y); pv[2] = f2tf(vv.z); pv[3] = f2tf(vv.w);
            }
            if (tid < 32) msm[tid] = maskb[posbase + t + tid];
            __syncthreads();

            // scores: S[16 rows][32 keys] per warp
            float sc[4][4];
#pragma unroll
            for (int nb = 0; nb < 4; nb++) {
                sc[nb][0] = sc[nb][1] = sc[nb][2] = sc[nb][3] = 0.f;
#pragma unroll
                for (int kk = 0; kk < 8; kk++) {
                    uint32_t bf[2];
                    int rn = nb * 8 + gid, c = kk * 8 + tig;
                    bf[0] = ks[rn * KPAD + c];
                    bf[1] = ks[rn * KPAD + c + 4];
                    mma8(sc[nb], qf[kk], bf);
                }
                float mk0 = msm[nb * 8 + 2 * tig], mk1 = msm[nb * 8 + 2 * tig + 1];
                sc[nb][0] += mk0; sc[nb][1] += mk1;
                sc[nb][2] += mk0; sc[nb][3] += mk1;
            }

            // online softmax (rows r = gid and r+8)
            float tm0 = -1e30f, tm1 = -1e30f;
#pragma unroll
            for (int nb = 0; nb < 4; nb++) {
                tm0 = fmaxf(tm0, fmaxf(sc[nb][0], sc[nb][1]));
                tm1 = fmaxf(tm1, fmaxf(sc[nb][2], sc[nb][3]));
            }
            tm0 = fmaxf(tm0, __shfl_xor_sync(FULL, tm0, 1));
            tm0 = fmaxf(tm0, __shfl_xor_sync(FULL, tm0, 2));
            tm1 = fmaxf(tm1, __shfl_xor_sync(FULL, tm1, 1));
            tm1 = fmaxf(tm1, __shfl_xor_sync(FULL, tm1, 2));
            float nm0 = fmaxf(m0, tm0), nm1 = fmaxf(m1, tm1);
            float cr0 = __expf(m0 - nm0), cr1 = __expf(m1 - nm1);
            m0 = nm0; m1 = nm1;
            l0 *= cr0; l1 *= cr1;

            uint32_t pt[4][4];
#pragma unroll
            for (int nb = 0; nb < 4; nb++) {
                float p0 = __expf(sc[nb][0] - m0), p1 = __expf(sc[nb][1] - m0);
                float p2 = __expf(sc[nb][2] - m1), p3 = __expf(sc[nb][3] - m1);
                l0 += p0 + p1; l1 += p2 + p3;
                pt[nb][0] = f2tf(p0); pt[nb][1] = f2tf(p1);
                pt[nb][2] = f2tf(p2); pt[nb][3] = f2tf(p3);
            }
#pragma unroll
            for (int nd = 0; nd < 8; nd++) {
                o[nd][0] *= cr0; o[nd][1] *= cr0;
                o[nd][2] *= cr1; o[nd][3] *= cr1;
            }

            // P (C-layout) -> A-fragments via quad shuffles, then P @ V
            const int srcA = (lane & ~3) | (tig >> 1);
            const int srcB = srcA + 2;
            const bool pk = tig & 1;
#pragma unroll
            for (int kc = 0; kc < 4; kc++) {
                uint32_t t0 = __shfl_sync(FULL, pt[kc][0], srcA);
                uint32_t t1 = __shfl_sync(FULL, pt[kc][1], srcA);
                uint32_t t2 = __shfl_sync(FULL, pt[kc][2], srcA);
                uint32_t t3 = __shfl_sync(FULL, pt[kc][3], srcA);
                uint32_t u0 = __shfl_sync(FULL, pt[kc][0], srcB);
                uint32_t u1 = __shfl_sync(FULL, pt[kc][1], srcB);
                uint32_t u2 = __shfl_sync(FULL, pt[kc][2], srcB);
                uint32_t u3 = __shfl_sync(FULL, pt[kc][3], srcB);
                uint32_t pa[4] = { pk ? t1 : t0, pk ? t3 : t2,
                                   pk ? u1 : u0, pk ? u3 : u2 };
#pragma unroll
                for (int nd = 0; nd < 8; nd++) {
                    uint32_t vf[2];
                    int rk = kc * 8 + tig, cn = nd * 8 + gid;
                    vf[0] = vs[rk * KPAD + cn];
                    vf[1] = vs[(rk + 4) * KPAD + cn];
                    mma8(o[nd], pa, vf);
                }
            }
        }
    }

    l0 += __shfl_xor_sync(FULL, l0, 1);
    l0 += __shfl_xor_sync(FULL, l0, 2);
    l1 += __shfl_xor_sync(FULL, l1, 1);
    l1 += __shfl_xor_sync(FULL, l1, 2);
    float i0 = 1.f / l0, i1 = 1.f / l1;

    const int s = warp * 16 + gid;
    float* ob  = out + ((size_t)b * S_ + s) * H_ + h * HD_;
    float* ob2 = out + ((size_t)b * S_ + s + 8) * H_ + h * HD_;
#pragma unroll
    for (int nd = 0; nd < 8; nd++) {
        int d = nd * 8 + 2 * tig;
        float2 v0 = { o[nd][0] * i0, o[nd][1] * i0 };
        float2 v1 = { o[nd][2] * i1, o[nd][3] * i1 };
        *(float2*)(ob + d)  = v0;
        *(float2*)(ob2 + d) = v1;
    }
}

// ---------------------------------------------------------------------------
extern "C" void kernel_launch(void* const* d_in, const int* in_sizes, int n_in,
                              void* d_out, int out_size)
{
    const float* hidden = (const float*)d_in[0];
    const float* mask   = (const float*)d_in[1];
    const float* Wq     = (const float*)d_in[2];
    const float* bq     = (const float*)d_in[3];
    const float* Wk     = (const float*)d_in[4];
    const float* bk     = (const float*)d_in[5];
    const float* Wv     = (const float*)d_in[6];
    const float* bv     = (const float*)d_in[7];
    const float* c0k    = (const float*)d_in[8];
    const float* c0v    = (const float*)d_in[9];
    const float* c1k    = (const float*)d_in[10];
    const float* c1v    = (const float*)d_in[11];

    float* out  = (float*)d_out;
    float* kout = out + (size_t)OUTSZ;
    float* vout = out + (size_t)2 * OUTSZ;

    cudaFuncSetAttribute(qkv_mma_kernel,
                         cudaFuncAttributeMaxDynamicSharedMemorySize, QKV_SMEM);

    dim3 g1(6, 120, 3);
    qkv_mma_kernel<<<g1, 256, QKV_SMEM>>>(hidden, Wq, bq, Wk, bk, Wv, bv, kout, vout);

    attn_mma_kernel<<<B_ * NH_, 128>>>(kout, vout, c0k, c0v, c1k, c1v, mask, out);
}